// round 7
// baseline (speedup 1.0000x reference)
#include <cuda_runtime.h>
#include <cuda_bf16.h>

#define BATCH 16
#define DIM   48
#define HID   16
#define CH    8
#define HH    256
#define WW    256
#define TILE  32
#define HT    34      // tile + halo
#define PITCH 35      // padded smem row pitch

typedef unsigned long long u64;

__constant__ float cW1[DIM*HID];
__constant__ float cB1[HID];
__constant__ float cGamma[CH];
__constant__ float cBeta[CH];
__constant__ float cDW[CH*9];
__constant__ float cDWB[CH];
__constant__ float cPW[CH*CH];
__constant__ float cPWB[CH];
__constant__ float cW2[CH*DIM];
__constant__ float cB2[DIM];

// ---------------- f32x2 packed primitives ----------------
#define F2U(x) __builtin_bit_cast(unsigned int, (x))
#define DUPC(x) ((((u64)F2U(x)) << 32) | (u64)F2U(x))

__device__ __forceinline__ u64 f2fma(u64 a, u64 b, u64 c) {
    u64 d; asm("fma.rn.f32x2 %0,%1,%2,%3;" : "=l"(d) : "l"(a), "l"(b), "l"(c)); return d;
}
__device__ __forceinline__ u64 f2mul(u64 a, u64 b) {
    u64 d; asm("mul.rn.f32x2 %0,%1,%2;" : "=l"(d) : "l"(a), "l"(b)); return d;
}
__device__ __forceinline__ u64 f2add(u64 a, u64 b) {
    u64 d; asm("add.rn.f32x2 %0,%1,%2;" : "=l"(d) : "l"(a), "l"(b)); return d;
}
__device__ __forceinline__ u64 pk(float lo, float hi) {
    u64 r; asm("mov.b64 %0,{%1,%2};" : "=l"(r) : "f"(lo), "f"(hi)); return r;
}
__device__ __forceinline__ void upk(float& lo, float& hi, u64 v) {
    asm("mov.b64 {%0,%1},%2;" : "=f"(lo), "=f"(hi) : "l"(v));
}

// ---------------- packed MUFU-free exact GELU (2 values at once) ----------------
// A&S 7.1.26 erf; bit-trick exp2 and rcp. fma/alu pipes only.
__device__ __forceinline__ u64 gelu2(u64 u2) {
    u64 t2 = f2mul(f2mul(u2, u2), DUPC(-0.72134752044f));   // -x^2*log2(e), x=|u|/sqrt2
    u64 fv = f2add(t2, DUPC(12582912.0f));                  // round to nearest int
    u64 fm = f2add(fv, DUPC(-12582912.0f));
    u64 r2 = f2fma(fm, DUPC(-1.0f), t2);                    // frac in [-0.5,0.5]
    u64 p2 = f2fma(r2, f2fma(r2, f2fma(r2, f2fma(r2, f2fma(r2,
                DUPC(0.0013333558f), DUPC(0.0096181291f)), DUPC(0.0555041087f)),
                DUPC(0.2402265070f)), DUPC(0.6931471806f)), DUPC(1.0f));
    float flo, fhi; upk(flo, fhi, fv);
    float slo = __int_as_float((__float_as_int(flo) << 23) + 0x3F800000);
    float shi = __int_as_float((__float_as_int(fhi) << 23) + 0x3F800000);
    u64 e2 = f2mul(p2, pk(slo, shi));                       // e^{-x^2}
    u64 d2 = f2fma(u2 & 0x7FFFFFFF7FFFFFFFULL, DUPC(0.23164190f), DUPC(1.0f));
    float dlo, dhi; upk(dlo, dhi, d2);
    u64 k2 = pk(__int_as_float(0x7EF311C3 - __float_as_int(dlo)),
                __int_as_float(0x7EF311C3 - __float_as_int(dhi)));
    u64 nd2 = f2mul(d2, DUPC(-1.0f));
    k2 = f2mul(k2, f2fma(nd2, k2, DUPC(2.0f)));
    k2 = f2mul(k2, f2fma(nd2, k2, DUPC(2.0f)));             // 1/(1+0.3275911*x)
    u64 poly = f2mul(k2, f2fma(k2, f2fma(k2, f2fma(k2, f2fma(k2,
                DUPC(0.5307027145f), DUPC(-0.7265760135f)), DUPC(0.7107068705f)),
                DUPC(-0.142248368f)), DUPC(0.127414796f)));
    u64 s2  = f2mul(poly, e2);                              // 0.5*erfc(x) in (0,0.5]
    u64 hs  = f2fma(s2, DUPC(-1.0f), DUPC(0.5f));           // 0.5-s  (>0)
    u64 phi = f2add(hs | (u2 & 0x8000000080000000ULL), DUPC(0.5f));
    return f2mul(u2, phi);
}

// scalar GELU for the halo path
__device__ __forceinline__ float gelu_fast(float u) {
    float t = u * u * -0.72134752044f;
    float f = t + 12582912.0f;
    int   i = __float_as_int(f);
    float r = t - (f - 12582912.0f);
    float p = fmaf(r, fmaf(r, fmaf(r, fmaf(r, fmaf(r, 0.0013333558f, 0.0096181291f),
                    0.0555041087f), 0.2402265070f), 0.6931471806f), 1.0f);
    float e = p * __int_as_float((i << 23) + 0x3F800000);
    float d = fmaf(fabsf(u), 0.23164190f, 1.0f);
    float k = __int_as_float(0x7EF311C3 - __float_as_int(d));
    k = k * fmaf(-d, k, 2.0f);
    k = k * fmaf(-d, k, 2.0f);
    float poly = k * fmaf(k, fmaf(k, fmaf(k, fmaf(k, 0.5307027145f, -0.7265760135f),
                      0.7107068705f), -0.142248368f), 0.127414796f);
    float s   = poly * e;
    float Phi = 0.5f + copysignf(0.5f - s, u);
    return u * Phi;
}

// ---------------- scalar single-token front (halo path) ----------------
__device__ __forceinline__ void token_front(const float* __restrict__ xtok,
                                            const float* __restrict__ sw1,  // duplicated u64 viewed as float, stride 2
                                            float* __restrict__ n) {
    float acc[HID];
    #pragma unroll
    for (int j = 0; j < HID; j++) acc[j] = cB1[j];

    const float4* xp4 = (const float4*)xtok;
    #pragma unroll
    for (int c4 = 0; c4 < DIM/4; c4++) {
        float4 v = xp4[c4];
        #pragma unroll
        for (int j = 0; j < HID; j++) {
            float a = acc[j];
            a = fmaf(v.x, sw1[2*((c4*4+0)*HID + j)], a);
            a = fmaf(v.y, sw1[2*((c4*4+1)*HID + j)], a);
            a = fmaf(v.z, sw1[2*((c4*4+2)*HID + j)], a);
            a = fmaf(v.w, sw1[2*((c4*4+3)*HID + j)], a);
            acc[j] = a;
        }
    }
    #pragma unroll
    for (int j = CH; j < HID; j++) acc[j] = gelu_fast(gelu_fast(acc[j]));

    float m = 0.f;
    #pragma unroll
    for (int j = 0; j < CH; j++) m += acc[CH + j];
    m *= (1.0f/CH);
    float var = 0.f;
    #pragma unroll
    for (int j = 0; j < CH; j++) { float dd = acc[CH+j] - m; var = fmaf(dd, dd, var); }
    var *= (1.0f/CH);
    float is = rsqrtf(var + 1e-5f);
    #pragma unroll
    for (int j = 0; j < CH; j++)
        n[j] = (acc[CH+j] - m) * is * cGamma[j] + cBeta[j];
}

__global__ void __launch_bounds__(256, 3)
fused_dclf_kernel(const float* __restrict__ x, float* __restrict__ out) {
    __shared__ u64 n_s2[CH/2][HT*PITCH];   // channel-pair packed n: 38080 B
    __shared__ u64 sW1d[DIM*HID];          // dup(w,w): 6144 B
    __shared__ u64 sW2d[CH*DIM];           // dup(w,w): 3072 B
    __shared__ u64 sDW2[4*9];              // (w_c, w_{c+1}) per tap: 288 B
    __shared__ u64 sPW2[4*8];              // (w_c, w_{c+1}) per k:   256 B

    const int b   = blockIdx.z;
    const int bx  = blockIdx.x * TILE;
    const int by  = blockIdx.y * TILE;
    const int tid = threadIdx.x;
    const int iy  = tid >> 3;           // 0..31
    const int ix0 = (tid & 7) << 2;     // 0,4,...,28
    const int gy  = by + iy;
    const int gx0 = bx + ix0;

    // ---- stage packed weights ----
    #pragma unroll
    for (int i = 0; i < 3; i++) { float w = cW1[tid + 256*i]; sW1d[tid + 256*i] = pk(w, w); }
    if (tid < 128) {
        #pragma unroll
        for (int i = 0; i < 3; i++) { float w = cW2[tid + 128*i]; sW2d[tid + 128*i] = pk(w, w); }
    }
    if (tid < 36) sDW2[tid] = pk(cDW[(tid/9)*18 + (tid%9)], cDW[(tid/9)*18 + 9 + (tid%9)]);
    if (tid < 32) sPW2[tid] = pk(cPW[(tid/8)*16 + (tid%8)], cPW[(tid/8)*16 + 8 + (tid%8)]);
    __syncthreads();

    const float* xbase = x + (size_t)b * (DIM*HH*WW);

    u64 g2[2][CH];   // pixel-pair packed: [pairgroup][channel]; starts as x1, becomes g

    // ---- phase 1a: interior quad as two pixel-PAIR passes through the GEMM ----
    #pragma unroll
    for (int pg = 0; pg < 2; pg++) {
        const float4* xp = (const float4*)(xbase + (size_t)(gy * WW + gx0 + 2*pg) * DIM);

        u64 acc2[HID];
        #pragma unroll
        for (int j = 0; j < HID; j++) { float bj = cB1[j]; acc2[j] = pk(bj, bj); }

        #pragma unroll
        for (int c4 = 0; c4 < DIM/4; c4++) {
            float4 a = xp[c4];
            float4 c = xp[DIM/4 + c4];
            u64 xv0 = pk(a.x, c.x), xv1 = pk(a.y, c.y);
            u64 xv2 = pk(a.z, c.z), xv3 = pk(a.w, c.w);
            #pragma unroll
            for (int j = 0; j < HID; j++) {
                u64 s = acc2[j];
                s = f2fma(xv0, sW1d[(c4*4+0)*HID + j], s);
                s = f2fma(xv1, sW1d[(c4*4+1)*HID + j], s);
                s = f2fma(xv2, sW1d[(c4*4+2)*HID + j], s);
                s = f2fma(xv3, sW1d[(c4*4+3)*HID + j], s);
                acc2[j] = s;
            }
        }

        #pragma unroll
        for (int j = 0; j < HID; j++) acc2[j] = gelu2(gelu2(acc2[j]));

        #pragma unroll
        for (int j = 0; j < CH; j++) g2[pg][j] = acc2[j];   // x1 half

        // layernorm over packed acc2[8..16)
        u64 m2 = acc2[CH];
        #pragma unroll
        for (int j = 1; j < CH; j++) m2 = f2add(m2, acc2[CH + j]);
        m2 = f2mul(m2, DUPC(0.125f));
        u64 d2[CH]; u64 v2 = 0ULL;
        #pragma unroll
        for (int j = 0; j < CH; j++) {
            d2[j] = f2fma(m2, DUPC(-1.0f), acc2[CH + j]);
            v2 = f2fma(d2[j], d2[j], v2);
        }
        v2 = f2fma(v2, DUPC(0.125f), DUPC(1e-5f));
        float vlo, vhi; upk(vlo, vhi, v2);
        float islo = rsqrtf(vlo), ishi = rsqrtf(vhi);

        float nlo[CH], nhi[CH];
        #pragma unroll
        for (int j = 0; j < CH; j++) {
            float dl, dh; upk(dl, dh, d2[j]);
            nlo[j] = fmaf(dl * islo, cGamma[j], cBeta[j]);
            nhi[j] = fmaf(dh * ishi, cGamma[j], cBeta[j]);
        }
        const int s0 = (iy+1)*PITCH + (ix0 + 2*pg + 1);
        #pragma unroll
        for (int cp = 0; cp < 4; cp++) {
            n_s2[cp][s0]     = pk(nlo[2*cp], nlo[2*cp+1]);
            n_s2[cp][s0 + 1] = pk(nhi[2*cp], nhi[2*cp+1]);
        }
    }

    // ---- phase 1b: halo ring (132 pixels, first 132 threads) ----
    if (tid < 132) {
        int hy, hx;
        if (tid < 34)       { hy = 0;   hx = tid;       }
        else if (tid < 68)  { hy = 33;  hx = tid - 34;  }
        else if (tid < 100) { hx = 0;   hy = tid - 67;  }
        else                { hx = 33;  hy = tid - 99;  }
        int gy2 = by + hy - 1;
        int gx2 = bx + hx - 1;
        float nv[CH];
        if (gy2 >= 0 && gy2 < HH && gx2 >= 0 && gx2 < WW) {
            token_front(xbase + (size_t)(gy2 * WW + gx2) * DIM, (const float*)sW1d, nv);
        } else {
            #pragma unroll
            for (int c = 0; c < CH; c++) nv[c] = 0.f;
        }
        int sidx = hy*PITCH + hx;
        #pragma unroll
        for (int cp = 0; cp < 4; cp++)
            n_s2[cp][sidx] = pk(nv[2*cp], nv[2*cp+1]);
    }

    __syncthreads();

    // ---- phase 2: packed dw-conv 3x3 + pw-conv 1x1, gate into g2 ----
    u64 dwb2[4], pwb2[4];
    #pragma unroll
    for (int cp = 0; cp < 4; cp++) {
        dwb2[cp] = pk(cDWB[2*cp], cDWB[2*cp+1]);
        pwb2[cp] = pk(cPWB[2*cp], cPWB[2*cp+1]);
    }

    #pragma unroll
    for (int pg = 0; pg < 2; pg++) {
        float mv[2][CH];     // gate multiplier (sp*ch) scalars per pixel of the pair
        #pragma unroll
        for (int h = 0; h < 2; h++) {
            const int base = (iy+1)*PITCH + (ix0 + 2*pg + h + 1);

            u64 nc2[4];
            float ncs[CH];
            #pragma unroll
            for (int cp = 0; cp < 4; cp++) {
                nc2[cp] = n_s2[cp][base];
                upk(ncs[2*cp], ncs[2*cp+1], nc2[cp]);
            }
            u64 ncd[CH];
            #pragma unroll
            for (int k = 0; k < CH; k++) ncd[k] = pk(ncs[k], ncs[k]);

            #pragma unroll
            for (int cp = 0; cp < 4; cp++) {
                u64 s2 = dwb2[cp];
                #pragma unroll
                for (int dy = 0; dy < 3; dy++) {
                    #pragma unroll
                    for (int dx = 0; dx < 3; dx++) {
                        s2 = f2fma(sDW2[cp*9 + dy*3 + dx],
                                   n_s2[cp][base + (dy-1)*PITCH + (dx-1)], s2);
                    }
                }
                u64 t2 = pwb2[cp];
                #pragma unroll
                for (int k = 0; k < CH; k++)
                    t2 = f2fma(sPW2[cp*8 + k], ncd[k], t2);
                u64 m2 = f2mul(s2, t2);
                upk(mv[h][2*cp], mv[h][2*cp+1], m2);
            }
        }
        #pragma unroll
        for (int c = 0; c < CH; c++)
            g2[pg][c] = f2mul(g2[pg][c], pk(mv[0][c], mv[1][c]));
    }

    // ---- phase 3: packed back GEMM g[8] @ W2[8x48] + b2, float4 stores ----
    float* outb = out + ((size_t)b*DIM*HH + gy)*WW + gx0;
    #pragma unroll
    for (int o = 0; o < DIM; o++) {
        float bo = cB2[o];
        u64 a0 = pk(bo, bo), a1 = a0;
        #pragma unroll
        for (int j = 0; j < CH; j++) {
            u64 w = sW2d[j*DIM + o];
            a0 = f2fma(g2[0][j], w, a0);
            a1 = f2fma(g2[1][j], w, a1);
        }
        float v0, v1, v2, v3;
        upk(v0, v1, a0);
        upk(v2, v3, a1);
        *(float4*)(outb + (size_t)o*HH*WW) = make_float4(v0, v1, v2, v3);
    }
}

extern "C" void kernel_launch(void* const* d_in, const int* in_sizes, int n_in,
                              void* d_out, int out_size) {
    cudaMemcpyToSymbolAsync(cW1,    d_in[1],  sizeof(cW1),    0, cudaMemcpyDeviceToDevice, 0);
    cudaMemcpyToSymbolAsync(cB1,    d_in[2],  sizeof(cB1),    0, cudaMemcpyDeviceToDevice, 0);
    cudaMemcpyToSymbolAsync(cGamma, d_in[3],  sizeof(cGamma), 0, cudaMemcpyDeviceToDevice, 0);
    cudaMemcpyToSymbolAsync(cBeta,  d_in[4],  sizeof(cBeta),  0, cudaMemcpyDeviceToDevice, 0);
    cudaMemcpyToSymbolAsync(cDW,    d_in[5],  sizeof(cDW),    0, cudaMemcpyDeviceToDevice, 0);
    cudaMemcpyToSymbolAsync(cDWB,   d_in[6],  sizeof(cDWB),   0, cudaMemcpyDeviceToDevice, 0);
    cudaMemcpyToSymbolAsync(cPW,    d_in[7],  sizeof(cPW),    0, cudaMemcpyDeviceToDevice, 0);
    cudaMemcpyToSymbolAsync(cPWB,   d_in[8],  sizeof(cPWB),   0, cudaMemcpyDeviceToDevice, 0);
    cudaMemcpyToSymbolAsync(cW2,    d_in[9],  sizeof(cW2),    0, cudaMemcpyDeviceToDevice, 0);
    cudaMemcpyToSymbolAsync(cB2,    d_in[10], sizeof(cB2),    0, cudaMemcpyDeviceToDevice, 0);

    dim3 grid(WW/TILE, HH/TILE, BATCH);   // (8, 8, 16)
    fused_dclf_kernel<<<grid, 256>>>((const float*)d_in[0], (float*)d_out);
}

// round 8
// speedup vs baseline: 3.1797x; 3.1797x over previous
#include <cuda_runtime.h>
#include <cuda_bf16.h>

#define BATCH 16
#define DIM   48
#define HID   16
#define CH    8
#define HH    256
#define WW    256
#define TILE  32
#define HT    34      // tile + halo
#define PITCH 35      // padded smem row pitch (conflict-free)

__constant__ float cW1[DIM*HID];
__constant__ float cB1[HID];
__constant__ float cGamma[CH];
__constant__ float cBeta[CH];
__constant__ float cDW[CH*9];
__constant__ float cDWB[CH];
__constant__ float cPW[CH*CH];
__constant__ float cPWB[CH];
__constant__ float cW2[CH*DIM];
__constant__ float cB2[DIM];

// ---------------- MUFU-free exact GELU ----------------
// A&S 7.1.26 erf (|eps|<=1.5e-7), bit-trick exp2 + bit-trick rcp (2 Newton).
__device__ __forceinline__ float gelu_fast(float u) {
    float t = u * u * -0.72134752044f;                // -x^2*log2(e), x=|u|/sqrt2
    float f = t + 12582912.0f;                        // round via magic const
    int   i = __float_as_int(f);
    float r = t - (f - 12582912.0f);
    float p = fmaf(r, fmaf(r, fmaf(r, fmaf(r, fmaf(r, 0.0013333558f, 0.0096181291f),
                    0.0555041087f), 0.2402265070f), 0.6931471806f), 1.0f);
    float e = p * __int_as_float((i << 23) + 0x3F800000);   // e^{-x^2}
    float d = fmaf(fabsf(u), 0.23164190f, 1.0f);
    float k = __int_as_float(0x7EF311C3 - __float_as_int(d));
    k = k * fmaf(-d, k, 2.0f);
    k = k * fmaf(-d, k, 2.0f);
    float poly = k * fmaf(k, fmaf(k, fmaf(k, fmaf(k, 0.5307027145f, -0.7265760135f),
                      0.7107068705f), -0.142248368f), 0.127414796f);
    float s   = poly * e;                             // 0.5*erfc(x)
    float Phi = 0.5f + copysignf(0.5f - s, u);
    return u * Phi;
}

// ---------------- single-token front (halo path), transposed W1 from smem ----------------
__device__ __forceinline__ void token_front(const float* __restrict__ xtok,
                                            const float* __restrict__ sW1t,  // [HID][DIM]
                                            float* __restrict__ n) {
    float acc[HID];
    #pragma unroll
    for (int j = 0; j < HID; j++) acc[j] = cB1[j];

    const float4* xp4 = (const float4*)xtok;
    #pragma unroll
    for (int c4 = 0; c4 < DIM/4; c4++) {
        float4 v = xp4[c4];
        #pragma unroll
        for (int j = 0; j < HID; j++) {
            float4 w = *(const float4*)&sW1t[j*DIM + c4*4];
            float a = acc[j];
            a = fmaf(v.x, w.x, a);
            a = fmaf(v.y, w.y, a);
            a = fmaf(v.z, w.z, a);
            a = fmaf(v.w, w.w, a);
            acc[j] = a;
        }
    }
    #pragma unroll
    for (int j = CH; j < HID; j++) acc[j] = gelu_fast(gelu_fast(acc[j]));

    float m = 0.f;
    #pragma unroll
    for (int j = 0; j < CH; j++) m += acc[CH + j];
    m *= (1.0f/CH);
    float var = 0.f;
    #pragma unroll
    for (int j = 0; j < CH; j++) { float dd = acc[CH+j] - m; var = fmaf(dd, dd, var); }
    var *= (1.0f/CH);
    float is = rsqrtf(var + 1e-5f);
    #pragma unroll
    for (int j = 0; j < CH; j++)
        n[j] = (acc[CH+j] - m) * is * cGamma[j] + cBeta[j];
}

__global__ void __launch_bounds__(512, 2)
fused_dclf_kernel(const float* __restrict__ x, float* __restrict__ out) {
    __shared__ float n_s[CH][HT*PITCH];   // 38080 B
    __shared__ float sW1t[HID*DIM];       // transposed W1: [HID][DIM], 3072 B
    __shared__ float sW2t[DIM*CH];        // transposed W2: [DIM][CH], 1536 B

    const int b   = blockIdx.z;
    const int bx  = blockIdx.x * TILE;
    const int by  = blockIdx.y * TILE;
    const int tid = threadIdx.x;
    const int iy  = tid >> 4;            // 0..31
    const int ix1 = (tid & 15) << 1;     // 0,2,...,30
    const int gy  = by + iy;
    const int gx0 = bx + ix1;

    // ---- stage transposed weights into smem ----
    for (int i = tid; i < HID*DIM; i += 512) {
        int j = i / DIM, c = i % DIM;
        sW1t[i] = cW1[c*HID + j];
    }
    if (tid < DIM*CH) {
        int o = tid >> 3, j = tid & 7;
        sW2t[tid] = cW2[j*DIM + o];
    }
    __syncthreads();

    const float* xbase = x + (size_t)b * (DIM*HH*WW);

    float x1r[2][CH];

    // ---- phase 1a: this thread's 2 adjacent pixels through the front ----
    {
        const float4* xp = (const float4*)(xbase + (size_t)(gy * WW + gx0) * DIM);

        float acc0[HID], acc1[HID];
        #pragma unroll
        for (int j = 0; j < HID; j++) { float bj = cB1[j]; acc0[j] = bj; acc1[j] = bj; }

        #pragma unroll
        for (int c4 = 0; c4 < DIM/4; c4++) {
            float4 a = xp[c4];
            float4 c = xp[DIM/4 + c4];
            #pragma unroll
            for (int j = 0; j < HID; j++) {
                float4 w = *(const float4*)&sW1t[j*DIM + c4*4];
                float s0 = acc0[j], s1 = acc1[j];
                s0 = fmaf(a.x, w.x, s0);   s1 = fmaf(c.x, w.x, s1);
                s0 = fmaf(a.y, w.y, s0);   s1 = fmaf(c.y, w.y, s1);
                s0 = fmaf(a.z, w.z, s0);   s1 = fmaf(c.z, w.z, s1);
                s0 = fmaf(a.w, w.w, s0);   s1 = fmaf(c.w, w.w, s1);
                acc0[j] = s0; acc1[j] = s1;
            }
        }

        #pragma unroll
        for (int h = 0; h < 2; h++) {
            float* acc = h ? acc1 : acc0;

            #pragma unroll
            for (int j = 0; j < HID; j++) acc[j] = gelu_fast(gelu_fast(acc[j]));

            #pragma unroll
            for (int j = 0; j < CH; j++) x1r[h][j] = acc[j];

            float m = 0.f;
            #pragma unroll
            for (int j = 0; j < CH; j++) m += acc[CH + j];
            m *= (1.0f/CH);
            float var = 0.f;
            #pragma unroll
            for (int j = 0; j < CH; j++) { float dd = acc[CH+j] - m; var = fmaf(dd, dd, var); }
            var *= (1.0f/CH);
            float is = rsqrtf(var + 1e-5f);

            const int sidx = (iy+1)*PITCH + (ix1+h+1);
            #pragma unroll
            for (int c = 0; c < CH; c++)
                n_s[c][sidx] = (acc[CH+c] - m) * is * cGamma[c] + cBeta[c];
        }
    }

    // ---- phase 1b: halo ring (132 pixels, first 132 threads) ----
    if (tid < 132) {
        int hy, hx;
        if (tid < 34)       { hy = 0;   hx = tid;       }
        else if (tid < 68)  { hy = 33;  hx = tid - 34;  }
        else if (tid < 100) { hx = 0;   hy = tid - 67;  }   // 1..32
        else                { hx = 33;  hy = tid - 99;  }   // 1..32
        int gy2 = by + hy - 1;
        int gx2 = bx + hx - 1;
        float nv[CH];
        if (gy2 >= 0 && gy2 < HH && gx2 >= 0 && gx2 < WW) {
            token_front(xbase + (size_t)(gy2 * WW + gx2) * DIM, sW1t, nv);
        } else {
            #pragma unroll
            for (int c = 0; c < CH; c++) nv[c] = 0.f;
        }
        int sidx = hy*PITCH + hx;
        #pragma unroll
        for (int c = 0; c < CH; c++) n_s[c][sidx] = nv[c];
    }

    __syncthreads();

    // ---- phase 2: dw-conv 3x3 + pw-conv 1x1 + gate (in place into x1r) ----
    #pragma unroll
    for (int h = 0; h < 2; h++) {
        const int base = (iy+1)*PITCH + (ix1+h+1);
        float nc[CH], sp[CH];
        #pragma unroll
        for (int c = 0; c < CH; c++) {
            nc[c] = n_s[c][base];
            float s = cDWB[c];
            #pragma unroll
            for (int dy = 0; dy < 3; dy++) {
                #pragma unroll
                for (int dx = 0; dx < 3; dx++) {
                    s = fmaf(cDW[c*9 + dy*3 + dx],
                             n_s[c][base + (dy-1)*PITCH + (dx-1)], s);
                }
            }
            sp[c] = s;
        }
        #pragma unroll
        for (int c = 0; c < CH; c++) {
            float t = cPWB[c];
            #pragma unroll
            for (int k = 0; k < CH; k++) t = fmaf(cPW[c*CH + k], nc[k], t);
            x1r[h][c] *= sp[c] * t;     // g = x1 * (sp * ch)
        }
    }

    // ---- phase 3: back GEMM g[8] @ W2[8x48] + b2, float2 stores ----
    float* outb = out + ((size_t)b*DIM*HH + gy)*WW + gx0;
    #pragma unroll
    for (int o = 0; o < DIM; o++) {
        float4 wa = *(const float4*)&sW2t[o*CH];
        float4 wb = *(const float4*)&sW2t[o*CH + 4];
        float bo = cB2[o];
        float s0 = bo, s1 = bo;
        s0 = fmaf(x1r[0][0], wa.x, s0);  s1 = fmaf(x1r[1][0], wa.x, s1);
        s0 = fmaf(x1r[0][1], wa.y, s0);  s1 = fmaf(x1r[1][1], wa.y, s1);
        s0 = fmaf(x1r[0][2], wa.z, s0);  s1 = fmaf(x1r[1][2], wa.z, s1);
        s0 = fmaf(x1r[0][3], wa.w, s0);  s1 = fmaf(x1r[1][3], wa.w, s1);
        s0 = fmaf(x1r[0][4], wb.x, s0);  s1 = fmaf(x1r[1][4], wb.x, s1);
        s0 = fmaf(x1r[0][5], wb.y, s0);  s1 = fmaf(x1r[1][5], wb.y, s1);
        s0 = fmaf(x1r[0][6], wb.z, s0);  s1 = fmaf(x1r[1][6], wb.z, s1);
        s0 = fmaf(x1r[0][7], wb.w, s0);  s1 = fmaf(x1r[1][7], wb.w, s1);
        *(float2*)(outb + (size_t)o*HH*WW) = make_float2(s0, s1);
    }
}

extern "C" void kernel_launch(void* const* d_in, const int* in_sizes, int n_in,
                              void* d_out, int out_size) {
    cudaMemcpyToSymbolAsync(cW1,    d_in[1],  sizeof(cW1),    0, cudaMemcpyDeviceToDevice, 0);
    cudaMemcpyToSymbolAsync(cB1,    d_in[2],  sizeof(cB1),    0, cudaMemcpyDeviceToDevice, 0);
    cudaMemcpyToSymbolAsync(cGamma, d_in[3],  sizeof(cGamma), 0, cudaMemcpyDeviceToDevice, 0);
    cudaMemcpyToSymbolAsync(cBeta,  d_in[4],  sizeof(cBeta),  0, cudaMemcpyDeviceToDevice, 0);
    cudaMemcpyToSymbolAsync(cDW,    d_in[5],  sizeof(cDW),    0, cudaMemcpyDeviceToDevice, 0);
    cudaMemcpyToSymbolAsync(cDWB,   d_in[6],  sizeof(cDWB),   0, cudaMemcpyDeviceToDevice, 0);
    cudaMemcpyToSymbolAsync(cPW,    d_in[7],  sizeof(cPW),    0, cudaMemcpyDeviceToDevice, 0);
    cudaMemcpyToSymbolAsync(cPWB,   d_in[8],  sizeof(cPWB),   0, cudaMemcpyDeviceToDevice, 0);
    cudaMemcpyToSymbolAsync(cW2,    d_in[9],  sizeof(cW2),    0, cudaMemcpyDeviceToDevice, 0);
    cudaMemcpyToSymbolAsync(cB2,    d_in[10], sizeof(cB2),    0, cudaMemcpyDeviceToDevice, 0);

    dim3 grid(WW/TILE, HH/TILE, BATCH);   // (8, 8, 16)
    fused_dclf_kernel<<<grid, 512>>>((const float*)d_in[0], (float*)d_out);
}

// round 11
// speedup vs baseline: 4.7502x; 1.4939x over previous
#include <cuda_runtime.h>
#include <cuda_bf16.h>

#define BATCH 16
#define DIM   48
#define HID   16
#define CH    8
#define HH    256
#define WW    256
#define HW    (HH*WW)          // 65536
#define TILE  32
#define HT    34               // tile + halo
#define PITCH 35               // padded smem row pitch (conflict-free)

__constant__ float cW1[DIM*HID];
__constant__ float cB1[HID];
__constant__ float cGamma[CH];
__constant__ float cBeta[CH];
__constant__ float cDW[CH*9];
__constant__ float cDWB[CH];
__constant__ float cPW[CH*CH];
__constant__ float cPWB[CH];
__constant__ float cW2[CH*DIM];
__constant__ float cB2[DIM];

// scratch: front-half outputs (allowed: __device__ global arrays)
__device__ float g_x1[(size_t)BATCH*HW*CH];   // token-major  [b*HW+p][8]
__device__ float g_n [(size_t)BATCH*CH*HW];   // chan-planar  [(b*8+c)*HW+p]

// ---------------- MUFU-free exact GELU ----------------
// A&S 7.1.26 erf (|eps|<=1.5e-7), bit-trick exp2 + bit-trick rcp (2 Newton).
__device__ __forceinline__ float gelu_fast(float u) {
    float t = u * u * -0.72134752044f;                // -x^2*log2(e), x=|u|/sqrt2
    float f = t + 12582912.0f;                        // round via magic const
    int   i = __float_as_int(f);
    float r = t - (f - 12582912.0f);
    float p = fmaf(r, fmaf(r, fmaf(r, fmaf(r, fmaf(r, 0.0013333558f, 0.0096181291f),
                    0.0555041087f), 0.2402265070f), 0.6931471806f), 1.0f);
    float e = p * __int_as_float((i << 23) + 0x3F800000);   // e^{-x^2}
    float d = fmaf(fabsf(u), 0.23164190f, 1.0f);
    float k = __int_as_float(0x7EF311C3 - __float_as_int(d));
    k = k * fmaf(-d, k, 2.0f);
    k = k * fmaf(-d, k, 2.0f);
    float poly = k * fmaf(k, fmaf(k, fmaf(k, fmaf(k, 0.5307027145f, -0.7265760135f),
                      0.7107068705f), -0.142248368f), 0.127414796f);
    float s   = poly * e;                             // 0.5*erfc(x)
    float Phi = 0.5f + copysignf(0.5f - s, u);
    return u * Phi;
}

// =================== Kernel 1: front (GEMM + 2xGELU + LN) ===================
__global__ void __launch_bounds__(256, 6)
front_kernel(const float* __restrict__ x) {
    __shared__ float sW1t[HID*DIM];      // transposed W1: [HID][DIM]

    const int tid = threadIdx.x;
    for (int i = tid; i < HID*DIM; i += 256) {
        int j = i / DIM, c = i % DIM;
        sW1t[i] = cW1[c*HID + j];
    }
    __syncthreads();

    const size_t tok = (size_t)blockIdx.x * 256 + tid;   // 0 .. BATCH*HW-1
    const float4* xp = (const float4*)(x + tok * DIM);

    float acc[HID];
    #pragma unroll
    for (int j = 0; j < HID; j++) acc[j] = cB1[j];

    #pragma unroll
    for (int c4 = 0; c4 < DIM/4; c4++) {
        float4 v = xp[c4];
        #pragma unroll
        for (int j = 0; j < HID; j++) {
            float4 w = *(const float4*)&sW1t[j*DIM + c4*4];
            float a = acc[j];
            a = fmaf(v.x, w.x, a);
            a = fmaf(v.y, w.y, a);
            a = fmaf(v.z, w.z, a);
            a = fmaf(v.w, w.w, a);
            acc[j] = a;
        }
    }

    #pragma unroll
    for (int j = 0; j < HID; j++) acc[j] = gelu_fast(gelu_fast(acc[j]));

    // x1 half -> token-major scratch (32B contiguous per thread)
    float4* x1p = (float4*)(g_x1 + tok * CH);
    x1p[0] = make_float4(acc[0], acc[1], acc[2], acc[3]);
    x1p[1] = make_float4(acc[4], acc[5], acc[6], acc[7]);

    // layernorm over acc[8..16) -> channel-planar scratch
    float m = 0.f;
    #pragma unroll
    for (int j = 0; j < CH; j++) m += acc[CH + j];
    m *= (1.0f/CH);
    float var = 0.f;
    #pragma unroll
    for (int j = 0; j < CH; j++) { float dd = acc[CH+j] - m; var = fmaf(dd, dd, var); }
    var *= (1.0f/CH);
    float is = rsqrtf(var + 1e-5f);

    const size_t b = tok >> 16;          // tok / HW
    const size_t p = tok & (HW - 1);     // tok % HW
    #pragma unroll
    for (int c = 0; c < CH; c++)
        g_n[((b*CH + c) << 16) + p] = (acc[CH+c] - m) * is * cGamma[c] + cBeta[c];
}

// =================== Kernel 2: conv + gate + back GEMM ===================
__global__ void __launch_bounds__(256, 4)
back_kernel(float* __restrict__ out) {
    __shared__ float n_s[CH][HT*PITCH];   // 38080 B
    __shared__ float sW2t[DIM*CH];        // transposed W2: [DIM][CH]

    const int b   = blockIdx.z;
    const int bx  = blockIdx.x * TILE;
    const int by  = blockIdx.y * TILE;
    const int tid = threadIdx.x;
    const int iy  = tid >> 3;            // 0..31
    const int ix1 = (tid & 7) << 2;      // 0,4,...,28 (4 px per thread)
    const int gy  = by + iy;
    const int gx0 = bx + ix1;

    // FIX (R9 bug): stage all DIM*CH=384 entries with a 256-thread block
    for (int i = tid; i < DIM*CH; i += 256) {
        int o = i >> 3, j = i & 7;
        sW2t[i] = cW2[j*DIM + o];
    }

    // ---- load n tile + halo from global (L2-resident) ----
    const float* nb = g_n + ((size_t)b*CH << 16);
    for (int i = tid; i < CH*HT*HT; i += 256) {
        int c  = i / (HT*HT);
        int r  = i % (HT*HT);
        int hy = r / HT, hx = r % HT;
        int gy2 = by + hy - 1, gx2 = bx + hx - 1;
        float v = 0.f;
        if (gy2 >= 0 && gy2 < HH && gx2 >= 0 && gx2 < WW)
            v = nb[((size_t)c << 16) + gy2*WW + gx2];
        n_s[c][hy*PITCH + hx] = v;
    }
    __syncthreads();

    // ---- x1 for this thread's 4 pixels ----
    float g[4][CH];
    {
        const float4* x1p = (const float4*)(g_x1 + (((size_t)b << 16) + gy*WW + gx0) * CH);
        #pragma unroll
        for (int p = 0; p < 4; p++) {
            float4 a = x1p[2*p], c = x1p[2*p+1];
            g[p][0]=a.x; g[p][1]=a.y; g[p][2]=a.z; g[p][3]=a.w;
            g[p][4]=c.x; g[p][5]=c.y; g[p][6]=c.z; g[p][7]=c.w;
        }
    }

    // ---- dw-conv 3x3 + pw-conv 1x1 + gate ----
    #pragma unroll
    for (int p = 0; p < 4; p++) {
        const int base = (iy+1)*PITCH + (ix1+p+1);
        float nc[CH], sp[CH];
        #pragma unroll
        for (int c = 0; c < CH; c++) {
            nc[c] = n_s[c][base];
            float s = cDWB[c];
            #pragma unroll
            for (int dy = 0; dy < 3; dy++) {
                #pragma unroll
                for (int dx = 0; dx < 3; dx++) {
                    s = fmaf(cDW[c*9 + dy*3 + dx],
                             n_s[c][base + (dy-1)*PITCH + (dx-1)], s);
                }
            }
            sp[c] = s;
        }
        #pragma unroll
        for (int c = 0; c < CH; c++) {
            float t = cPWB[c];
            #pragma unroll
            for (int k = 0; k < CH; k++) t = fmaf(cPW[c*CH + k], nc[k], t);
            g[p][c] *= sp[c] * t;        // g = x1 * (sp * ch)
        }
    }

    // ---- back GEMM g[8] @ W2[8x48] + b2, float4 stores per channel plane ----
    float* outb = out + ((size_t)b*DIM*HH + gy)*WW + gx0;
    #pragma unroll
    for (int o = 0; o < DIM; o++) {
        float4 wa = *(const float4*)&sW2t[o*CH];
        float4 wb = *(const float4*)&sW2t[o*CH + 4];
        float bo = cB2[o];
        float vv[4];
        #pragma unroll
        for (int p = 0; p < 4; p++) {
            float s = bo;
            s = fmaf(g[p][0], wa.x, s);
            s = fmaf(g[p][1], wa.y, s);
            s = fmaf(g[p][2], wa.z, s);
            s = fmaf(g[p][3], wa.w, s);
            s = fmaf(g[p][4], wb.x, s);
            s = fmaf(g[p][5], wb.y, s);
            s = fmaf(g[p][6], wb.z, s);
            s = fmaf(g[p][7], wb.w, s);
            vv[p] = s;
        }
        *(float4*)(outb + (size_t)o*HW) = make_float4(vv[0], vv[1], vv[2], vv[3]);
    }
}

extern "C" void kernel_launch(void* const* d_in, const int* in_sizes, int n_in,
                              void* d_out, int out_size) {
    cudaMemcpyToSymbolAsync(cW1,    d_in[1],  sizeof(cW1),    0, cudaMemcpyDeviceToDevice, 0);
    cudaMemcpyToSymbolAsync(cB1,    d_in[2],  sizeof(cB1),    0, cudaMemcpyDeviceToDevice, 0);
    cudaMemcpyToSymbolAsync(cGamma, d_in[3],  sizeof(cGamma), 0, cudaMemcpyDeviceToDevice, 0);
    cudaMemcpyToSymbolAsync(cBeta,  d_in[4],  sizeof(cBeta),  0, cudaMemcpyDeviceToDevice, 0);
    cudaMemcpyToSymbolAsync(cDW,    d_in[5],  sizeof(cDW),    0, cudaMemcpyDeviceToDevice, 0);
    cudaMemcpyToSymbolAsync(cDWB,   d_in[6],  sizeof(cDWB),   0, cudaMemcpyDeviceToDevice, 0);
    cudaMemcpyToSymbolAsync(cPW,    d_in[7],  sizeof(cPW),    0, cudaMemcpyDeviceToDevice, 0);
    cudaMemcpyToSymbolAsync(cPWB,   d_in[8],  sizeof(cPWB),   0, cudaMemcpyDeviceToDevice, 0);
    cudaMemcpyToSymbolAsync(cW2,    d_in[9],  sizeof(cW2),    0, cudaMemcpyDeviceToDevice, 0);
    cudaMemcpyToSymbolAsync(cB2,    d_in[10], sizeof(cB2),    0, cudaMemcpyDeviceToDevice, 0);

    const float* x = (const float*)d_in[0];
    float* out = (float*)d_out;

    front_kernel<<<BATCH*HW/256, 256>>>(x);                 // 4096 blocks
    dim3 grid2(WW/TILE, HH/TILE, BATCH);                    // (8, 8, 16)
    back_kernel<<<grid2, 256>>>(out);
}